// round 1
// baseline (speedup 1.0000x reference)
#include <cuda_runtime.h>
#include <cstdint>

#define BB 4
#define TT 512
#define CIN 2048
#define DD 128
#define HW 49
#define LK 101
#define HALF 50

// fp32 accumulator for projected (pre-normalization) features, y[b][t][d]
__device__ float g_y[BB * TT * DD];

// ---------------- Kernel 0: zero the accumulator ----------------
__global__ void k_zero() {
    int i = blockIdx.x * blockDim.x + threadIdx.x;
    float4* p = (float4*)g_y;
    if (i < (BB * TT * DD) / 4) p[i] = make_float4(0.f, 0.f, 0.f, 0.f);
}

// ---------------- Kernel A: fused spatial-sum + projection ----------------
// grid: (16 t-chunks, 8 c-chunks, 4 batches), block: 256 threads
// Per block: c-chunk of 256 channels x t-chunk of 32 frames.
// Loops 4 sub-chunks of 64 channels:
//   - stage Wp tile [64c x 128d] transposed in smem (pad 132)
//   - 8 warps compute 2048 spatial sums (warp-per-row, 49 floats each)
//   - register-tiled GEMM from smem, acc[4d][4t] per thread
// Epilogue: atomicAdd partials into g_y.
__global__ __launch_bounds__(256) void k_sumproj(const float* __restrict__ x1,
                                                 const float* __restrict__ x2,
                                                 const float* __restrict__ Wp) {
    __shared__ float sW[64 * 132];  // [cc][d], stride 132 (conflict-free, float4-aligned)
    __shared__ float sS[64 * 32];   // [cc][tl] == linear row index

    const int tid  = threadIdx.x;
    const int w    = tid >> 5;
    const int lane = tid & 31;
    const int tx   = tid & 7;   // t-group: t = t0 + tx*4 + i
    const int ty   = tid >> 3;  // d-group: d = ty*4 + j
    const int t0   = blockIdx.x * 32;
    const int c0   = blockIdx.y * 256;
    const int b    = blockIdx.z;

    float acc[4][4];
#pragma unroll
    for (int j = 0; j < 4; j++)
#pragma unroll
        for (int i = 0; i < 4; i++) acc[j][i] = 0.f;

    for (int sub = 0; sub < 4; sub++) {
        const int cbase = c0 + sub * 64;

        // stage Wp tile transposed: sW[cc*132 + d] = Wp[d*2048 + cbase + cc]
#pragma unroll
        for (int it = 0; it < 32; it++) {
            int idx = tid + it * 256;
            int d   = idx >> 6;
            int cc  = idx & 63;
            sW[cc * 132 + d] = Wp[d * CIN + cbase + cc];
        }

        // spatial sums: 64c x 32t = 2048 rows, warp streams 256 contiguous rows
        for (int k = 0; k < 256; k += 2) {
            int r0  = w * 256 + k;      // r = cc*32 + tl
            int cc  = r0 >> 5;
            int tl  = r0 & 31;
            int cin = cbase + cc;
            const float* base = (cin < 1024) ? x1 : x2;
            const float* p0 = base + (((size_t)b * 1024 + (cin & 1023)) * TT + (t0 + tl)) * HW;
            const float* p1 = p0 + HW;  // r0 even -> r0+1 same cc, tl+1

            float a0 = p0[lane];
            float a1 = p1[lane];
            float b0 = (lane < 17) ? p0[lane + 32] : 0.f;
            float b1 = (lane < 17) ? p1[lane + 32] : 0.f;
            float s0 = a0 + b0;
            float s1 = a1 + b1;
#pragma unroll
            for (int o = 16; o; o >>= 1) {
                s0 += __shfl_xor_sync(0xffffffffu, s0, o);
                s1 += __shfl_xor_sync(0xffffffffu, s1, o);
            }
            if (lane == 0) {
                sS[r0]     = s0;
                sS[r0 + 1] = s1;
            }
        }
        __syncthreads();

        // GEMM: acc[j][i] += sW[c][ty*4+j] * sS[c][tx*4+i]
        const float4* W4 = (const float4*)sW;  // row stride 33 float4
        const float4* S4 = (const float4*)sS;  // row stride 8 float4
#pragma unroll 16
        for (int c = 0; c < 64; c++) {
            float4 wv = W4[c * 33 + ty];
            float4 sv = S4[c * 8 + tx];
            acc[0][0] += wv.x * sv.x; acc[0][1] += wv.x * sv.y;
            acc[0][2] += wv.x * sv.z; acc[0][3] += wv.x * sv.w;
            acc[1][0] += wv.y * sv.x; acc[1][1] += wv.y * sv.y;
            acc[1][2] += wv.y * sv.z; acc[1][3] += wv.y * sv.w;
            acc[2][0] += wv.z * sv.x; acc[2][1] += wv.z * sv.y;
            acc[2][2] += wv.z * sv.z; acc[2][3] += wv.z * sv.w;
            acc[3][0] += wv.w * sv.x; acc[3][1] += wv.w * sv.y;
            acc[3][2] += wv.w * sv.z; acc[3][3] += wv.w * sv.w;
        }
        __syncthreads();
    }

#pragma unroll
    for (int j = 0; j < 4; j++) {
        int d = ty * 4 + j;
#pragma unroll
        for (int i = 0; i < 4; i++) {
            int t = t0 + tx * 4 + i;
            atomicAdd(&g_y[(b * TT + t) * DD + d], acc[j][i]);
        }
    }
}

// ---------------- Kernel B: L2-normalize each row of g_y ----------------
__global__ void k_norm() {
    int row = blockIdx.x;   // B*T rows
    int d   = threadIdx.x;  // 128
    float v = g_y[row * DD + d];
    float s = v * v;
#pragma unroll
    for (int o = 16; o; o >>= 1) s += __shfl_xor_sync(0xffffffffu, s, o);
    __shared__ float ws[4];
    if ((d & 31) == 0) ws[d >> 5] = s;
    __syncthreads();
    float tot   = ws[0] + ws[1] + ws[2] + ws[3];
    float scale = 1.f / fmaxf(sqrtf(tot), 1e-12f);
    g_y[row * DD + d] = v * scale;
}

// ---------------- Kernel C: banded similarity + FC + relu ----------------
// grid: (64 t-chunks of 8, 4 batches), block 256, dynamic smem.
#define TCH 8
#define XROWS (TCH + 2 * HALF)  // 108
#define SMEM_C_BYTES ((XROWS * 129 + LK * 129 + TCH * 104 + 128) * 4)

__global__ __launch_bounds__(256) void k_band(const float* __restrict__ Wf,
                                              const float* __restrict__ bf,
                                              float* __restrict__ out) {
    extern __shared__ float sm[];
    float* xw  = sm;                    // [108][129] window of normalized rows
    float* wfT = xw + XROWS * 129;      // [l][129] transposed FC weights
    float* win = wfT + LK * 129;        // [8][104] banded similarities
    float* bfs = win + TCH * 104;       // [128]

    const int tid = threadIdx.x;
    const int b   = blockIdx.y;
    const int t0  = blockIdx.x * TCH;

    // stage window rows (zero pad out-of-range)
    for (int idx = tid; idx < XROWS * 128; idx += 256) {
        int r = idx >> 7, k = idx & 127;
        int g = t0 - HALF + r;
        xw[r * 129 + k] = (g >= 0 && g < TT) ? g_y[(b * TT + g) * DD + k] : 0.f;
    }
    // stage Wf transposed
    for (int idx = tid; idx < 128 * LK; idx += 256) {
        int o = idx / LK, l = idx % LK;
        wfT[l * 129 + o] = Wf[o * LK + l];
    }
    if (tid < 128) bfs[tid] = bf[tid];
    __syncthreads();

    // banded similarities: 8t x 101l dots of length 128; task = (t_l, lg), l = lg + 26j
    if (tid < TCH * 26) {
        int t_l = tid / 26, lg = tid % 26;
        const float* arow = xw + (HALF + t_l) * 129;
        int r0 = t_l + lg;
        int r1 = t_l + lg + 26;
        int r2 = t_l + lg + 52;
        int r3v = t_l + lg + 78;
        int r3 = (r3v <= XROWS - 1) ? r3v : 0;  // guard (invalid when l>=101)
        const float* p0 = xw + r0 * 129;
        const float* p1 = xw + r1 * 129;
        const float* p2 = xw + r2 * 129;
        const float* p3 = xw + r3 * 129;
        float d0 = 0.f, d1 = 0.f, d2 = 0.f, d3 = 0.f;
#pragma unroll 8
        for (int k = 0; k < 128; k++) {
            float a = arow[k];
            d0 += a * p0[k];
            d1 += a * p1[k];
            d2 += a * p2[k];
            d3 += a * p3[k];
        }
        win[t_l * 104 + lg]      = d0;
        win[t_l * 104 + lg + 26] = d1;
        win[t_l * 104 + lg + 52] = d2;
        if (lg + 78 < LK) win[t_l * 104 + lg + 78] = d3;
    }
    __syncthreads();

    // FC: out[b, t, o] = relu(bf[o] + sum_l win[t][l] * Wf[o][l])
    int o  = tid & 127;
    int hh = tid >> 7;  // 0/1 -> 4 t each
    float a0 = bfs[o], a1 = bfs[o], a2 = bfs[o], a3 = bfs[o];
    const float* w0 = win + (hh * 4 + 0) * 104;
    const float* w1 = win + (hh * 4 + 1) * 104;
    const float* w2 = win + (hh * 4 + 2) * 104;
    const float* w3 = win + (hh * 4 + 3) * 104;
#pragma unroll 4
    for (int l = 0; l < LK; l++) {
        float wf = wfT[l * 129 + o];
        a0 += wf * w0[l];
        a1 += wf * w1[l];
        a2 += wf * w2[l];
        a3 += wf * w3[l];
    }
    int tb = t0 + hh * 4;
    out[((b * TT + tb + 0) << 7) + o] = fmaxf(a0, 0.f);
    out[((b * TT + tb + 1) << 7) + o] = fmaxf(a1, 0.f);
    out[((b * TT + tb + 2) << 7) + o] = fmaxf(a2, 0.f);
    out[((b * TT + tb + 3) << 7) + o] = fmaxf(a3, 0.f);
}

extern "C" void kernel_launch(void* const* d_in, const int* in_sizes, int n_in,
                              void* d_out, int out_size) {
    const float* x1 = (const float*)d_in[0];
    const float* x2 = (const float*)d_in[1];
    const float* Wp = (const float*)d_in[2];
    const float* Wf = (const float*)d_in[3];
    const float* bf = (const float*)d_in[4];
    float* out = (float*)d_out;

    // zero accumulator
    k_zero<<<(BB * TT * DD / 4 + 255) / 256, 256>>>();

    // fused spatial-sum + projection
    dim3 gA(16, 8, BB);
    k_sumproj<<<gA, 256>>>(x1, x2, Wp);

    // normalize
    k_norm<<<BB * TT, 128>>>();

    // banded similarity + FC
    static bool attr_done = false;
    if (!attr_done) {
        cudaFuncSetAttribute(k_band, cudaFuncAttributeMaxDynamicSharedMemorySize,
                             SMEM_C_BYTES);
        attr_done = true;
    }
    dim3 gC(TT / TCH, BB);
    k_band<<<gC, 256, SMEM_C_BYTES>>>(Wf, bf, out);
}

// round 3
// speedup vs baseline: 1.2285x; 1.2285x over previous
#include <cuda_runtime.h>
#include <cstdint>

#define BB 4
#define TT 512
#define CIN 2048
#define DD 128
#define HW 49
#define LK 101
#define HALF 50

// fp32 accumulator for projected (pre-normalization) features, y[b][t][d]
__device__ float g_y[BB * TT * DD];

// ---------------- Kernel 0: zero the accumulator ----------------
__global__ void k_zero() {
    int i = blockIdx.x * blockDim.x + threadIdx.x;
    float4* p = (float4*)g_y;
    if (i < (BB * TT * DD) / 4) p[i] = make_float4(0.f, 0.f, 0.f, 0.f);
}

// ---------------- Kernel A: fused spatial-sum + projection ----------------
// grid: (16 t-chunks, 8 c-chunks, 4 batches), block: 256 threads.
// Per block: 256 channels x 32 frames, in 4 sub-chunks of 64 channels.
// Per sub-chunk, each warp handles 8 channels; per channel it stages the
// 32 contiguous rows (1568 floats) to smem via coalesced float4, then each
// lane sums its own 49-float row via conflict-free strided LDS (stride 49,
// gcd(49 mod 32, 32) = 1). No shuffles. Then a register-tiled GEMM with the
// staged Wp tile, atomicAdd epilogue into g_y.
#define SMEM_A_FLOATS (64 * 132 + 2048 + 8 * 1568)
#define SMEM_A_BYTES (SMEM_A_FLOATS * 4)

__global__ __launch_bounds__(256) void k_sumproj(const float* __restrict__ x1,
                                                 const float* __restrict__ x2,
                                                 const float* __restrict__ Wp) {
    extern __shared__ float dsm[];
    float* sW = dsm;             // [64][132] Wp tile transposed, padded
    float* sS = sW + 64 * 132;   // [64*32] spatial sums, row = cc*32+tl
    const int tid  = threadIdx.x;
    const int w    = tid >> 5;
    const int lane = tid & 31;
    float* stg = sS + 2048 + w * 1568;  // per-warp staging, 16B aligned
    float4* stg4 = (float4*)stg;

    const int tx = tid & 7;   // t-group: t = t0 + tx*4 + i
    const int ty = tid >> 3;  // d-group: d = ty*4 + j
    const int t0 = blockIdx.x * 32;
    const int c0 = blockIdx.y * 256;
    const int b  = blockIdx.z;

    float acc[4][4];
#pragma unroll
    for (int j = 0; j < 4; j++)
#pragma unroll
        for (int i = 0; i < 4; i++) acc[j][i] = 0.f;

    for (int sub = 0; sub < 4; sub++) {
        const int cbase = c0 + sub * 64;

        // stage Wp tile transposed: sW[cc*132 + d] = Wp[d*2048 + cbase + cc]
#pragma unroll
        for (int it = 0; it < 32; it++) {
            int idx = tid + it * 256;
            int d   = idx >> 6;
            int cc  = idx & 63;
            sW[cc * 132 + d] = Wp[d * CIN + cbase + cc];
        }

        // spatial sums: warp w handles channels cc = w*8 .. w*8+7
#pragma unroll 1
        for (int i = 0; i < 8; i++) {
            int cc  = w * 8 + i;
            int cin = cbase + cc;
            const float* base = (cin < 1024) ? x1 : x2;
            const float4* s4 = (const float4*)(base +
                (((size_t)b * 1024 + (cin & 1023)) * TT + t0) * HW);

            // 392 float4 = 1568 floats, coalesced, batched for MLP
            float4 v[12];
#pragma unroll
            for (int k = 0; k < 12; k++) v[k] = s4[lane + 32 * k];
            float4 vt;
            if (lane < 8) vt = s4[384 + lane];
#pragma unroll
            for (int k = 0; k < 12; k++) stg4[lane + 32 * k] = v[k];
            if (lane < 8) stg4[384 + lane] = vt;
            __syncwarp();

            // lane sums its own row (conflict-free: stride 49)
            const float* r = stg + lane * 49;
            float a0 = 0.f, a1 = 0.f, a2 = 0.f, a3 = 0.f;
#pragma unroll
            for (int j = 0; j < 48; j += 4) {
                a0 += r[j];
                a1 += r[j + 1];
                a2 += r[j + 2];
                a3 += r[j + 3];
            }
            sS[cc * 32 + lane] = (a0 + a1) + (a2 + a3) + r[48];
            __syncwarp();
        }
        __syncthreads();

        // GEMM: acc[j][i] += sW[c][ty*4+j] * sS[c][tx*4+i]
        const float4* W4 = (const float4*)sW;  // row stride 33 float4
        const float4* S4 = (const float4*)sS;  // row stride 8 float4
#pragma unroll 16
        for (int c = 0; c < 64; c++) {
            float4 wv = W4[c * 33 + ty];
            float4 sv = S4[c * 8 + tx];
            acc[0][0] += wv.x * sv.x; acc[0][1] += wv.x * sv.y;
            acc[0][2] += wv.x * sv.z; acc[0][3] += wv.x * sv.w;
            acc[1][0] += wv.y * sv.x; acc[1][1] += wv.y * sv.y;
            acc[1][2] += wv.y * sv.z; acc[1][3] += wv.y * sv.w;
            acc[2][0] += wv.z * sv.x; acc[2][1] += wv.z * sv.y;
            acc[2][2] += wv.z * sv.z; acc[2][3] += wv.z * sv.w;
            acc[3][0] += wv.w * sv.x; acc[3][1] += wv.w * sv.y;
            acc[3][2] += wv.w * sv.z; acc[3][3] += wv.w * sv.w;
        }
        __syncthreads();
    }

#pragma unroll
    for (int j = 0; j < 4; j++) {
        int d = ty * 4 + j;
#pragma unroll
        for (int i = 0; i < 4; i++) {
            int t = t0 + tx * 4 + i;
            atomicAdd(&g_y[(b * TT + t) * DD + d], acc[j][i]);
        }
    }
}

// ---------------- Kernel B: L2-normalize each row of g_y ----------------
__global__ void k_norm() {
    int row = blockIdx.x;   // B*T rows
    int d   = threadIdx.x;  // 128
    float v = g_y[row * DD + d];
    float s = v * v;
#pragma unroll
    for (int o = 16; o; o >>= 1) s += __shfl_xor_sync(0xffffffffu, s, o);
    __shared__ float ws[4];
    if ((d & 31) == 0) ws[d >> 5] = s;
    __syncthreads();
    float tot   = ws[0] + ws[1] + ws[2] + ws[3];
    float scale = 1.f / fmaxf(sqrtf(tot), 1e-12f);
    g_y[row * DD + d] = v * scale;
}

// ---------------- Kernel C: banded similarity + FC + relu ----------------
// grid: (64 t-chunks of 8, 4 batches), block 256, dynamic smem.
// Rows padded to stride 132 (16B aligned) so the similarity dots run on
// float4 LDS (4x fewer shared-load instructions than scalar).
#define TCH 8
#define XROWS (TCH + 2 * HALF)  // 108
#define STR 132
#define SMEM_C_BYTES ((XROWS * STR + LK * STR + TCH * 104 + 128) * 4)

__global__ __launch_bounds__(256) void k_band(const float* __restrict__ Wf,
                                              const float* __restrict__ bf,
                                              float* __restrict__ out) {
    extern __shared__ float sm[];
    float* xw  = sm;                    // [108][132] window of normalized rows
    float* wfT = xw + XROWS * STR;      // [l][132] transposed FC weights
    float* win = wfT + LK * STR;        // [8][104] banded similarities
    float* bfs = win + TCH * 104;       // [128]

    const int tid = threadIdx.x;
    const int b   = blockIdx.y;
    const int t0  = blockIdx.x * TCH;

    // stage window rows (zero pad out-of-range)
    for (int idx = tid; idx < XROWS * 128; idx += 256) {
        int r = idx >> 7, k = idx & 127;
        int g = t0 - HALF + r;
        xw[r * STR + k] = (g >= 0 && g < TT) ? g_y[(b * TT + g) * DD + k] : 0.f;
    }
    // stage Wf transposed
    for (int idx = tid; idx < 128 * LK; idx += 256) {
        int o = idx / LK, l = idx % LK;
        wfT[l * STR + o] = Wf[o * LK + l];
    }
    if (tid < 128) bfs[tid] = bf[tid];
    __syncthreads();

    // banded similarities: 8t x 101l dots of length 128; l = lg + 26j
    if (tid < TCH * 26) {
        int t_l = tid / 26, lg = tid % 26;
        const float4* A = (const float4*)(xw + (HALF + t_l) * STR);
        int r0 = t_l + lg;
        int r3v = t_l + lg + 78;
        int r3 = (r3v <= XROWS - 1) ? r3v : 0;  // guard (invalid when l>=101)
        const float4* P0 = (const float4*)(xw + r0 * STR);
        const float4* P1 = (const float4*)(xw + (r0 + 26) * STR);
        const float4* P2 = (const float4*)(xw + (r0 + 52) * STR);
        const float4* P3 = (const float4*)(xw + r3 * STR);
        float d0 = 0.f, d1 = 0.f, d2 = 0.f, d3 = 0.f;
#pragma unroll 8
        for (int k = 0; k < 32; k++) {
            float4 a  = A[k];
            float4 q0 = P0[k];
            float4 q1 = P1[k];
            float4 q2 = P2[k];
            float4 q3 = P3[k];
            d0 += a.x * q0.x + a.y * q0.y + a.z * q0.z + a.w * q0.w;
            d1 += a.x * q1.x + a.y * q1.y + a.z * q1.z + a.w * q1.w;
            d2 += a.x * q2.x + a.y * q2.y + a.z * q2.z + a.w * q2.w;
            d3 += a.x * q3.x + a.y * q3.y + a.z * q3.z + a.w * q3.w;
        }
        win[t_l * 104 + lg]      = d0;
        win[t_l * 104 + lg + 26] = d1;
        win[t_l * 104 + lg + 52] = d2;
        if (lg + 78 < LK) win[t_l * 104 + lg + 78] = d3;
    }
    __syncthreads();

    // FC: out[b, t, o] = relu(bf[o] + sum_l win[t][l] * Wf[o][l])
    int o  = tid & 127;
    int hh = tid >> 7;  // 0/1 -> 4 t each
    float a0 = bfs[o], a1 = bfs[o], a2 = bfs[o], a3 = bfs[o];
    const float* w0 = win + (hh * 4 + 0) * 104;
    const float* w1 = win + (hh * 4 + 1) * 104;
    const float* w2 = win + (hh * 4 + 2) * 104;
    const float* w3 = win + (hh * 4 + 3) * 104;
#pragma unroll 4
    for (int l = 0; l < LK; l++) {
        float wf = wfT[l * STR + o];
        a0 += wf * w0[l];
        a1 += wf * w1[l];
        a2 += wf * w2[l];
        a3 += wf * w3[l];
    }
    int tb = t0 + hh * 4;
    out[((b * TT + tb + 0) << 7) + o] = fmaxf(a0, 0.f);
    out[((b * TT + tb + 1) << 7) + o] = fmaxf(a1, 0.f);
    out[((b * TT + tb + 2) << 7) + o] = fmaxf(a2, 0.f);
    out[((b * TT + tb + 3) << 7) + o] = fmaxf(a3, 0.f);
}

extern "C" void kernel_launch(void* const* d_in, const int* in_sizes, int n_in,
                              void* d_out, int out_size) {
    const float* x1 = (const float*)d_in[0];
    const float* x2 = (const float*)d_in[1];
    const float* Wp = (const float*)d_in[2];
    const float* Wf = (const float*)d_in[3];
    const float* bf = (const float*)d_in[4];
    float* out = (float*)d_out;

    cudaFuncSetAttribute(k_sumproj, cudaFuncAttributeMaxDynamicSharedMemorySize,
                         SMEM_A_BYTES);
    cudaFuncSetAttribute(k_band, cudaFuncAttributeMaxDynamicSharedMemorySize,
                         SMEM_C_BYTES);

    // zero accumulator
    k_zero<<<(BB * TT * DD / 4 + 255) / 256, 256>>>();

    // fused spatial-sum + projection
    dim3 gA(16, 8, BB);
    k_sumproj<<<gA, 256, SMEM_A_BYTES>>>(x1, x2, Wp);

    // normalize
    k_norm<<<BB * TT, 128>>>();

    // banded similarity + FC
    dim3 gC(TT / TCH, BB);
    k_band<<<gC, 256, SMEM_C_BYTES>>>(Wf, bf, out);
}

// round 4
// speedup vs baseline: 1.3294x; 1.0822x over previous
#include <cuda_runtime.h>
#include <cstdint>

#define BB 4
#define TT 512
#define CIN 2048
#define DD 128
#define HW 49
#define LK 101
#define HALF 50

// fp32 accumulator for projected (pre-normalization) features, y[b][t][d]
__device__ float g_y[BB * TT * DD];

// ---------------- Kernel 0: zero the accumulator ----------------
__global__ void k_zero() {
    int i = blockIdx.x * blockDim.x + threadIdx.x;
    float4* p = (float4*)g_y;
    if (i < (BB * TT * DD) / 4) p[i] = make_float4(0.f, 0.f, 0.f, 0.f);
}

// ---------------- cp.async helpers ----------------
__device__ __forceinline__ void cp16(uint32_t dst, const void* src) {
    asm volatile("cp.async.cg.shared.global [%0], [%1], 16;\n" ::"r"(dst), "l"(src));
}
__device__ __forceinline__ void cp_commit() {
    asm volatile("cp.async.commit_group;\n");
}
__device__ __forceinline__ void cp_wait1() {
    asm volatile("cp.async.wait_group 1;\n");
}
__device__ __forceinline__ void cp_wait0() {
    asm volatile("cp.async.wait_group 0;\n");
}

// ---------------- Kernel A: fused spatial-sum + projection ----------------
// grid: (16 t-chunks, 16 c-chunks, 4 batches), block 256.
// Per block: 128 channels x 32 frames, 2 sub-chunks of 64 channels.
// Per warp: 16 channels total, double-buffered cp.async staging (GMEM->smem
// direct, no register round-trip, 2 channels in flight at all times, the
// pipeline runs across sub-chunk __syncthreads). Row sums via conflict-free
// strided LDS (stride 49). Register-tiled GEMM per sub-chunk, atomicAdd
// epilogue into g_y.
#define CHW (HW * 32)                 // 1568 floats per channel stage
#define SMEM_A_FLOATS (64 * 132 + 2048 + 8 * 2 * CHW)
#define SMEM_A_BYTES (SMEM_A_FLOATS * 4)

__global__ __launch_bounds__(256) void k_sumproj(const float* __restrict__ x1,
                                                 const float* __restrict__ x2,
                                                 const float* __restrict__ Wp) {
    extern __shared__ float dsm[];
    float* sW = dsm;             // [64][132] Wp tile transposed, padded
    float* sS = sW + 64 * 132;   // [64*32] spatial sums, row = cc*32+tl
    const int tid  = threadIdx.x;
    const int w    = tid >> 5;
    const int lane = tid & 31;
    float* stg = sS + 2048 + w * (2 * CHW);  // per-warp double buffer
    const uint32_t stg_u32 = (uint32_t)__cvta_generic_to_shared(stg);

    const int tx = tid & 7;   // t-group: t = t0 + tx*4 + i
    const int ty = tid >> 3;  // d-group: d = ty*4 + j
    const int t0 = blockIdx.x * 32;
    const int c0 = blockIdx.y * 128;
    const int b  = blockIdx.z;

    // channel q (0..15): sub = q>>3, cc_local = w*8 + (q&7)
    auto src_of = [&](int q) -> const float4* {
        int cin = c0 + (q >> 3) * 64 + w * 8 + (q & 7);
        const float* base = (cin < 1024) ? x1 : x2;
        return (const float4*)(base +
            (((size_t)b * 1024 + (cin & 1023)) * TT + t0) * HW);
    };
    auto prefetch = [&](int q) {
        const float4* s4 = src_of(q);
        uint32_t d = stg_u32 + (uint32_t)(q & 1) * (CHW * 4);
#pragma unroll
        for (int j = 0; j < 12; j++)
            cp16(d + (lane + 32 * j) * 16, s4 + lane + 32 * j);
        if (lane < 8) cp16(d + (384 + lane) * 16, s4 + 384 + lane);
        cp_commit();
    };

    float acc[4][4];
#pragma unroll
    for (int j = 0; j < 4; j++)
#pragma unroll
        for (int i = 0; i < 4; i++) acc[j][i] = 0.f;

    prefetch(0);
    prefetch(1);

    for (int sub = 0; sub < 2; sub++) {
        const int cbase = c0 + sub * 64;

        // stage Wp tile transposed: sW[cc*132 + d] = Wp[d*2048 + cbase + cc]
#pragma unroll
        for (int it = 0; it < 32; it++) {
            int idx = tid + it * 256;
            int d   = idx >> 6;
            int cc  = idx & 63;
            sW[cc * 132 + d] = Wp[d * CIN + cbase + cc];
        }

        // row sums, pipelined
#pragma unroll 1
        for (int i = 0; i < 8; i++) {
            int q = sub * 8 + i;
            if (q == 15) cp_wait0(); else cp_wait1();
            __syncwarp();

            const float* r = stg + (q & 1) * CHW + lane * HW;
            float a0 = 0.f, a1 = 0.f, a2 = 0.f, a3 = 0.f;
#pragma unroll
            for (int j = 0; j < 48; j += 4) {
                a0 += r[j];
                a1 += r[j + 1];
                a2 += r[j + 2];
                a3 += r[j + 3];
            }
            int cc = w * 8 + i;
            sS[cc * 32 + lane] = (a0 + a1) + (a2 + a3) + r[48];
            __syncwarp();
            if (q + 2 < 16) prefetch(q + 2);
        }
        __syncthreads();

        // GEMM: acc[j][i] += sW[c][ty*4+j] * sS[c][tx*4+i]
        const float4* W4 = (const float4*)sW;  // row stride 33 float4
        const float4* S4 = (const float4*)sS;  // row stride 8 float4
#pragma unroll 16
        for (int c = 0; c < 64; c++) {
            float4 wv = W4[c * 33 + ty];
            float4 sv = S4[c * 8 + tx];
            acc[0][0] += wv.x * sv.x; acc[0][1] += wv.x * sv.y;
            acc[0][2] += wv.x * sv.z; acc[0][3] += wv.x * sv.w;
            acc[1][0] += wv.y * sv.x; acc[1][1] += wv.y * sv.y;
            acc[1][2] += wv.y * sv.z; acc[1][3] += wv.y * sv.w;
            acc[2][0] += wv.z * sv.x; acc[2][1] += wv.z * sv.y;
            acc[2][2] += wv.z * sv.z; acc[2][3] += wv.z * sv.w;
            acc[3][0] += wv.w * sv.x; acc[3][1] += wv.w * sv.y;
            acc[3][2] += wv.w * sv.z; acc[3][3] += wv.w * sv.w;
        }
        __syncthreads();
    }

#pragma unroll
    for (int j = 0; j < 4; j++) {
        int d = ty * 4 + j;
#pragma unroll
        for (int i = 0; i < 4; i++) {
            int t = t0 + tx * 4 + i;
            atomicAdd(&g_y[(b * TT + t) * DD + d], acc[j][i]);
        }
    }
}

// ---------------- Kernel C: normalize + banded similarity + FC + relu ------
// grid: (64 t-chunks of 8, 4 batches), block 256.
// Phase 1 stages the 108-row window AND L2-normalizes each row on the fly
// (k_norm fused away). Phase 2 uses all 256 threads (t_l = tid>>5,
// l = (tid&31) + 32j). Phase 3 reads Wf/bf straight from gmem (L2-resident,
// heavy cross-block reuse) — smem drops to ~59KB -> 3 CTAs/SM.
#define TCH 8
#define XROWS (TCH + 2 * HALF)  // 108
#define STR 132
#define SMEM_C_BYTES ((XROWS * STR + TCH * 104) * 4)

__global__ __launch_bounds__(256) void k_band(const float* __restrict__ Wf,
                                              const float* __restrict__ bf,
                                              float* __restrict__ out) {
    extern __shared__ float sm[];
    float* xw  = sm;               // [108][132] normalized window rows
    float* win = xw + XROWS * STR; // [8][104] banded similarities

    const int tid  = threadIdx.x;
    const int w    = tid >> 5;
    const int lane = tid & 31;
    const int b    = blockIdx.y;
    const int t0   = blockIdx.x * TCH;

    // Phase 1: stage + normalize. Warp handles rows w, w+8, ...
    const float4* gy4 = (const float4*)g_y;
    for (int r = w; r < XROWS; r += 8) {
        int g = t0 - HALF + r;
        float4 v = make_float4(0.f, 0.f, 0.f, 0.f);
        if (g >= 0 && g < TT) v = gy4[((size_t)b * TT + g) * 32 + lane];
        float s = v.x * v.x + v.y * v.y + v.z * v.z + v.w * v.w;
#pragma unroll
        for (int o = 16; o; o >>= 1) s += __shfl_xor_sync(0xffffffffu, s, o);
        float sc = 1.f / fmaxf(sqrtf(s), 1e-12f);
        float4 nv = make_float4(v.x * sc, v.y * sc, v.z * sc, v.w * sc);
        ((float4*)(xw + r * STR))[lane] = nv;
    }
    __syncthreads();

    // Phase 2: banded similarities, all 256 threads.
    // thread -> t_l = tid>>5, l = l0 + 32j (l0 = tid&31), j = 0..3 (l<101)
    {
        int t_l = tid >> 5;
        int l0  = tid & 31;
        const float4* A = (const float4*)(xw + (HALF + t_l) * STR);
        const float4* P0 = (const float4*)(xw + (t_l + l0) * STR);
        const float4* P1 = (const float4*)(xw + (t_l + l0 + 32) * STR);
        const float4* P2 = (const float4*)(xw + (t_l + l0 + 64) * STR);
        int r3 = (l0 + 96 < LK) ? (t_l + l0 + 96) : 0;  // guard
        const float4* P3 = (const float4*)(xw + r3 * STR);
        float d0 = 0.f, d1 = 0.f, d2 = 0.f, d3 = 0.f;
#pragma unroll 8
        for (int k = 0; k < 32; k++) {
            float4 a  = A[k];
            float4 q0 = P0[k];
            float4 q1 = P1[k];
            float4 q2 = P2[k];
            float4 q3 = P3[k];
            d0 += a.x * q0.x + a.y * q0.y + a.z * q0.z + a.w * q0.w;
            d1 += a.x * q1.x + a.y * q1.y + a.z * q1.z + a.w * q1.w;
            d2 += a.x * q2.x + a.y * q2.y + a.z * q2.z + a.w * q2.w;
            d3 += a.x * q3.x + a.y * q3.y + a.z * q3.z + a.w * q3.w;
        }
        win[t_l * 104 + l0]      = d0;
        win[t_l * 104 + l0 + 32] = d1;
        win[t_l * 104 + l0 + 64] = d2;
        if (l0 + 96 < LK) win[t_l * 104 + l0 + 96] = d3;
    }
    __syncthreads();

    // Phase 3: FC from gmem weights. out[b,t,o] = relu(bf[o] + sum_l win*Wf)
    int o  = tid & 127;
    int hh = tid >> 7;  // 0/1 -> 4 t each
    float bias = __ldg(bf + o);
    float a0 = bias, a1 = bias, a2 = bias, a3 = bias;
    const float* wrow = Wf + o * LK;
    const float* w0 = win + (hh * 4 + 0) * 104;
    const float* w1 = win + (hh * 4 + 1) * 104;
    const float* w2 = win + (hh * 4 + 2) * 104;
    const float* w3 = win + (hh * 4 + 3) * 104;
#pragma unroll 4
    for (int l = 0; l < LK; l++) {
        float wf = __ldg(wrow + l);
        a0 += wf * w0[l];
        a1 += wf * w1[l];
        a2 += wf * w2[l];
        a3 += wf * w3[l];
    }
    int tb = t0 + hh * 4;
    out[((b * TT + tb + 0) << 7) + o] = fmaxf(a0, 0.f);
    out[((b * TT + tb + 1) << 7) + o] = fmaxf(a1, 0.f);
    out[((b * TT + tb + 2) << 7) + o] = fmaxf(a2, 0.f);
    out[((b * TT + tb + 3) << 7) + o] = fmaxf(a3, 0.f);
}

extern "C" void kernel_launch(void* const* d_in, const int* in_sizes, int n_in,
                              void* d_out, int out_size) {
    const float* x1 = (const float*)d_in[0];
    const float* x2 = (const float*)d_in[1];
    const float* Wp = (const float*)d_in[2];
    const float* Wf = (const float*)d_in[3];
    const float* bf = (const float*)d_in[4];
    float* out = (float*)d_out;

    cudaFuncSetAttribute(k_sumproj, cudaFuncAttributeMaxDynamicSharedMemorySize,
                         SMEM_A_BYTES);
    cudaFuncSetAttribute(k_band, cudaFuncAttributeMaxDynamicSharedMemorySize,
                         SMEM_C_BYTES);

    // zero accumulator
    k_zero<<<(BB * TT * DD / 4 + 255) / 256, 256>>>();

    // fused spatial-sum + projection
    dim3 gA(16, 16, BB);
    k_sumproj<<<gA, 256, SMEM_A_BYTES>>>(x1, x2, Wp);

    // fused normalize + banded similarity + FC
    dim3 gC(TT / TCH, BB);
    k_band<<<gC, 256, SMEM_C_BYTES>>>(Wf, bf, out);
}